// round 3
// baseline (speedup 1.0000x reference)
#include <cuda_runtime.h>
#include <cuda_bf16.h>
#include <math.h>

// Problem constants
#define SEQ   2048
#define INDIM 256
#define H     512
#define R4H   2048   // 4*H
#define CTAS_PER_SIDE 64
#define TOTAL_CTAS    128

// ---------------- device scratch (static: no allocation allowed) ----------------
__device__ float    g_x[2][SEQ][INDIM];    // gathered embeddings, 4 MB
__device__ float    g_xp[2][SEQ][R4H];     // input projections + bias, 32 MB
__device__ float    g_h[2][2][H];          // double-buffered hidden state per side
__device__ unsigned g_cnt[2];              // per-side barrier counters (monotonic per launch)
__device__ unsigned g_fin;                 // final barrier

// ---------------- sync helpers ----------------
__device__ __forceinline__ unsigned ld_acq(const unsigned* p) {
    unsigned v;
    asm volatile("ld.acquire.gpu.global.u32 %0, [%1];" : "=r"(v) : "l"(p) : "memory");
    return v;
}
__device__ __forceinline__ void red_release_add1(unsigned* p) {
    asm volatile("red.release.gpu.global.add.u32 [%0], 1;" :: "l"(p) : "memory");
}

// fast activations (ex2-based, ~1e-6 rel err; avoid tanh.approx ~1e-3)
__device__ __forceinline__ float fast_sigmoid(float x) {
    return 1.0f / (1.0f + __expf(-x));
}
__device__ __forceinline__ float fast_tanh(float x) {
    // tanh(x) = 1 - 2/(exp(2x)+1)
    return 1.0f - 2.0f / (__expf(2.0f * x) + 1.0f);
}

// ---------------- kernel 0: gather embeddings + reset state ----------------
// Token indices are int32 (JAX materializes jnp.int64 as int32 with x64 disabled).
__global__ void __launch_bounds__(256) init_gather(const int* __restrict__ lidx,
                                                   const int* __restrict__ ridx,
                                                   const float* __restrict__ emb) {
    int bx = blockIdx.x;              // 0..4095
    int side = bx >> 11;              // 0..1
    int t = bx & (SEQ - 1);
    const int* idxp = side ? ridx : lidx;
    long long tok = (long long)idxp[t];
    g_x[side][t][threadIdx.x] = emb[tok * (long long)INDIM + threadIdx.x];

    if (bx == 0) {
        if (threadIdx.x < 2) g_cnt[threadIdx.x] = 0u;
        if (threadIdx.x == 2) g_fin = 0u;
        float* hp = &g_h[0][0][0];
        #pragma unroll
        for (int i = threadIdx.x; i < 2 * 2 * H; i += 256) hp[i] = 0.0f;
    }
}

// ---------------- kernel 1: xp = x @ W_ih^T + (b_ih + b_hh) ----------------
// C[2048 t][2048 r] = sum_k A[t][k] * B[r][k] + bias[r]; A,B both K-major.
// 128x128 tile, BK=16, 256 threads, 8x8 microtile.
__global__ void __launch_bounds__(256) gemm_xp(const float* __restrict__ W_ih,
                                               const float* __restrict__ b_ih,
                                               const float* __restrict__ b_hh) {
    int s  = blockIdx.z;
    int bm = blockIdx.y * 128;   // t offset
    int bn = blockIdx.x * 128;   // r offset
    const float* A = &g_x[s][0][0];   // [2048][256]
    const float* B = W_ih;            // [2048][256]

    __shared__ float As[16][128];
    __shared__ float Bs[16][128];

    int tid = threadIdx.x;
    int tx = tid & 15;       // 0..15 -> n
    int ty = tid >> 4;       // 0..15 -> m

    float acc[8][8];
    #pragma unroll
    for (int i = 0; i < 8; i++)
        #pragma unroll
        for (int jj = 0; jj < 8; jj++) acc[i][jj] = 0.0f;

    for (int k0 = 0; k0 < INDIM; k0 += 16) {
        #pragma unroll
        for (int i = 0; i < 2; i++) {
            int fidx = tid * 2 + i;          // 0..511
            int row = fidx >> 2;             // 0..127
            int kq  = fidx & 3;              // 0..3
            float4 v = *(const float4*)(A + (size_t)(bm + row) * INDIM + k0 + kq * 4);
            As[kq * 4 + 0][row] = v.x;
            As[kq * 4 + 1][row] = v.y;
            As[kq * 4 + 2][row] = v.z;
            As[kq * 4 + 3][row] = v.w;
            float4 u = *(const float4*)(B + (size_t)(bn + row) * INDIM + k0 + kq * 4);
            Bs[kq * 4 + 0][row] = u.x;
            Bs[kq * 4 + 1][row] = u.y;
            Bs[kq * 4 + 2][row] = u.z;
            Bs[kq * 4 + 3][row] = u.w;
        }
        __syncthreads();

        #pragma unroll
        for (int k = 0; k < 16; k++) {
            float a[8], b[8];
            *(float4*)(a)     = *(const float4*)&As[k][ty * 8];
            *(float4*)(a + 4) = *(const float4*)&As[k][ty * 8 + 4];
            *(float4*)(b)     = *(const float4*)&Bs[k][tx * 8];
            *(float4*)(b + 4) = *(const float4*)&Bs[k][tx * 8 + 4];
            #pragma unroll
            for (int mi = 0; mi < 8; mi++)
                #pragma unroll
                for (int ni = 0; ni < 8; ni++)
                    acc[mi][ni] += a[mi] * b[ni];
        }
        __syncthreads();
    }

    float bias[8];
    #pragma unroll
    for (int ni = 0; ni < 8; ni++) {
        int n = bn + tx * 8 + ni;
        bias[ni] = b_ih[n] + b_hh[n];
    }
    #pragma unroll
    for (int mi = 0; mi < 8; mi++) {
        int m = bm + ty * 8 + mi;
        float* cp = &g_xp[s][m][bn + tx * 8];
        float4 v0, v1;
        v0.x = acc[mi][0] + bias[0]; v0.y = acc[mi][1] + bias[1];
        v0.z = acc[mi][2] + bias[2]; v0.w = acc[mi][3] + bias[3];
        v1.x = acc[mi][4] + bias[4]; v1.y = acc[mi][5] + bias[5];
        v1.z = acc[mi][6] + bias[6]; v1.w = acc[mi][7] + bias[7];
        *(float4*)(cp)     = v0;
        *(float4*)(cp + 4) = v1;
    }
}

// ---------------- kernel 2: persistent LSTM scan ----------------
// 128 CTAs: CTAs [0,64) = side L, [64,128) = side R. 8 warps/CTA, 1 warp = 1 hidden unit.
// W_hh rows for unit j (gates i,f,g,o) live in registers: w[4][16] per lane.
__global__ void __launch_bounds__(256) scan_kernel(const float* __restrict__ W_hh,
                                                   float* __restrict__ out) {
    const int side = blockIdx.x >> 6;          // /64
    const int cta  = blockIdx.x & 63;
    const int warp = threadIdx.x >> 5;
    const int lane = threadIdx.x & 31;
    const int j = cta * 8 + warp;              // hidden unit 0..511

    // Load recurrent weights into registers (one time)
    float w[4][16];
    #pragma unroll
    for (int g = 0; g < 4; g++) {
        const float* row = W_hh + (size_t)(g * H + j) * H + lane * 16;
        #pragma unroll
        for (int q = 0; q < 4; q++) {
            float4 v = *(const float4*)(row + q * 4);
            w[g][q * 4 + 0] = v.x; w[g][q * 4 + 1] = v.y;
            w[g][q * 4 + 2] = v.z; w[g][q * 4 + 3] = v.w;
        }
    }

    const float* xps = &g_xp[side][0][0];
    unsigned* cnt = &g_cnt[side];
    float c = 0.0f;

    // prefetch xp for t=0 (uniform within warp; L2 broadcast)
    float xg0 = xps[0 * H + j];
    float xg1 = xps[1 * H + j];
    float xg2 = xps[2 * H + j];
    float xg3 = xps[3 * H + j];

    for (int t = 0; t < SEQ; t++) {
        const int rb = t & 1;          // read buffer
        const int wb = rb ^ 1;         // write buffer

        // Each lane loads its 16 consecutive h values straight from L2 (.cg
        // bypasses possibly-stale L1; h was written by other SMs).
        const float4* hb = (const float4*)&g_h[side][rb][lane * 16];
        float4 h0 = __ldcg(hb + 0);
        float4 h1 = __ldcg(hb + 1);
        float4 h2 = __ldcg(hb + 2);
        float4 h3 = __ldcg(hb + 3);
        float hr[16];
        hr[0]=h0.x; hr[1]=h0.y; hr[2]=h0.z; hr[3]=h0.w;
        hr[4]=h1.x; hr[5]=h1.y; hr[6]=h1.z; hr[7]=h1.w;
        hr[8]=h2.x; hr[9]=h2.y; hr[10]=h2.z; hr[11]=h2.w;
        hr[12]=h3.x; hr[13]=h3.y; hr[14]=h3.z; hr[15]=h3.w;

        float acc0 = 0.0f, acc1 = 0.0f, acc2 = 0.0f, acc3 = 0.0f;
        #pragma unroll
        for (int i = 0; i < 16; i++) {
            acc0 += w[0][i] * hr[i];
            acc1 += w[1][i] * hr[i];
            acc2 += w[2][i] * hr[i];
            acc3 += w[3][i] * hr[i];
        }
        // warp-wide sum (butterfly leaves total in every lane)
        #pragma unroll
        for (int off = 16; off > 0; off >>= 1) {
            acc0 += __shfl_xor_sync(0xFFFFFFFFu, acc0, off);
            acc1 += __shfl_xor_sync(0xFFFFFFFFu, acc1, off);
            acc2 += __shfl_xor_sync(0xFFFFFFFFu, acc2, off);
            acc3 += __shfl_xor_sync(0xFFFFFFFFu, acc3, off);
        }

        float gi = fast_sigmoid(acc0 + xg0);
        float gf = fast_sigmoid(acc1 + xg1);
        float gg = fast_tanh(acc2 + xg2);
        float go = fast_sigmoid(acc3 + xg3);
        c = gf * c + gi * gg;
        float hval = go * fast_tanh(c);
        if (lane == 0) g_h[side][wb][j] = hval;

        // prefetch xp for next step BEFORE the barrier wait (hides L2 latency)
        if (t + 1 < SEQ) {
            const float* xn = xps + (size_t)(t + 1) * R4H;
            xg0 = xn[0 * H + j];
            xg1 = xn[1 * H + j];
            xg2 = xn[2 * H + j];
            xg3 = xn[3 * H + j];
        }

        // per-side grid barrier: release-RED (no L1-flushing threadfence) + acquire poll
        __syncthreads();
        if (threadIdx.x == 0) {
            red_release_add1(cnt);
            unsigned tgt = (unsigned)CTAS_PER_SIDE * (unsigned)(t + 1);
            while (ld_acq(cnt) < tgt) { }
        }
        __syncthreads();
    }

    // final cross-side barrier + output
    __shared__ float sred[8];
    if (threadIdx.x == 0) {
        red_release_add1(&g_fin);
    }
    if (blockIdx.x == 0) {
        if (threadIdx.x == 0) {
            while (ld_acq(&g_fin) < (unsigned)TOTAL_CTAS) { }
        }
        __syncthreads();
        // final h lives in buffer (SEQ & 1) = 0
        float sv = 0.0f;
        for (int i = threadIdx.x; i < H; i += 256)
            sv += fabsf(__ldcg(&g_h[0][0][i]) - __ldcg(&g_h[1][0][i]));
        #pragma unroll
        for (int off = 16; off > 0; off >>= 1)
            sv += __shfl_xor_sync(0xFFFFFFFFu, sv, off);
        if (lane == 0) sred[warp] = sv;
        __syncthreads();
        if (threadIdx.x == 0) {
            float s = 0.0f;
            #pragma unroll
            for (int wdx = 0; wdx < 8; wdx++) s += sred[wdx];
            out[0] = expf(-s);
        }
    }
}

// ---------------- launch ----------------
extern "C" void kernel_launch(void* const* d_in, const int* in_sizes, int n_in,
                              void* d_out, int out_size) {
    const int* lidx = (const int*)d_in[0];
    const int* ridx = (const int*)d_in[1];
    const float* emb  = (const float*)d_in[2];
    const float* W_ih = (const float*)d_in[3];
    const float* W_hh = (const float*)d_in[4];
    const float* b_ih = (const float*)d_in[5];
    const float* b_hh = (const float*)d_in[6];
    float* out = (float*)d_out;

    init_gather<<<4096, 256>>>(lidx, ridx, emb);
    gemm_xp<<<dim3(16, 16, 2), 256>>>(W_ih, b_ih, b_hh);
    scan_kernel<<<TOTAL_CTAS, 256>>>(W_hh, out);
}

// round 4
// speedup vs baseline: 2.8683x; 2.8683x over previous
#include <cuda_runtime.h>
#include <cuda_bf16.h>
#include <math.h>

// Problem constants
#define SEQ   2048
#define INDIM 256
#define H     512
#define R4H   2048   // 4*H
#define CTAS_PER_SIDE 64
#define TOTAL_CTAS    128

// ---------------- device scratch (static: no allocation allowed) ----------------
__device__ float              g_x[2][SEQ][INDIM];   // gathered embeddings, 4 MB
__device__ float              g_xp[2][SEQ][R4H];    // input projections + bias, 32 MB
// Tagged hidden state: [side][buf][unit] = {lo: f32 h value, hi: u32 step tag}
__device__ unsigned long long g_ht[2][2][H];

// ---------------- tagged pair helpers (8B stores/loads are atomic) ----------------
__device__ __forceinline__ void store_pair(unsigned long long* p, float v, unsigned tag) {
    unsigned long long u = ((unsigned long long)tag << 32) | (unsigned long long)__float_as_uint(v);
    asm volatile("st.global.cg.b64 [%0], %1;" :: "l"(p), "l"(u) : "memory");
}
__device__ __forceinline__ float poll_pair(const unsigned long long* p, unsigned tag) {
    unsigned long long u;
    do {
        asm volatile("ld.global.cg.b64 %0, [%1];" : "=l"(u) : "l"(p) : "memory");
    } while ((unsigned)(u >> 32) != tag);
    return __uint_as_float((unsigned)u);
}

// fast activations (ex2-based, ~1e-6 rel err; avoid tanh.approx ~1e-3)
__device__ __forceinline__ float fast_sigmoid(float x) {
    return 1.0f / (1.0f + __expf(-x));
}
__device__ __forceinline__ float fast_tanh(float x) {
    return 1.0f - 2.0f / (__expf(2.0f * x) + 1.0f);
}

// ---------------- kernel 0: gather embeddings + reset tagged state ----------------
// Token indices are int32 (JAX materializes jnp.int64 as int32 with x64 disabled).
__global__ void __launch_bounds__(256) init_gather(const int* __restrict__ lidx,
                                                   const int* __restrict__ ridx,
                                                   const float* __restrict__ emb) {
    int bx = blockIdx.x;              // 0..4095
    int side = bx >> 11;              // 0..1
    int t = bx & (SEQ - 1);
    const int* idxp = side ? ridx : lidx;
    long long tok = (long long)idxp[t];
    g_x[side][t][threadIdx.x] = emb[tok * (long long)INDIM + threadIdx.x];

    if (bx == 0) {
        // buf0: value 0.0f, tag 0 (valid input for step 0). buf1: tag sentinel.
        int i = threadIdx.x;                          // 0..255
        for (int s = 0; s < 2; s++) {
            g_ht[s][0][2 * i]     = 0ull;
            g_ht[s][0][2 * i + 1] = 0ull;
            g_ht[s][1][2 * i]     = 0xFFFFFFFF00000000ull;
            g_ht[s][1][2 * i + 1] = 0xFFFFFFFF00000000ull;
        }
    }
}

// ---------------- kernel 1: xp = x @ W_ih^T + (b_ih + b_hh) ----------------
// C[2048 t][2048 r] = sum_k A[t][k] * B[r][k] + bias[r]; A,B both K-major.
// 128x128 tile, BK=16, 256 threads, 8x8 microtile.
__global__ void __launch_bounds__(256) gemm_xp(const float* __restrict__ W_ih,
                                               const float* __restrict__ b_ih,
                                               const float* __restrict__ b_hh) {
    int s  = blockIdx.z;
    int bm = blockIdx.y * 128;   // t offset
    int bn = blockIdx.x * 128;   // r offset
    const float* A = &g_x[s][0][0];   // [2048][256]
    const float* B = W_ih;            // [2048][256]

    __shared__ float As[16][128];
    __shared__ float Bs[16][128];

    int tid = threadIdx.x;
    int tx = tid & 15;       // 0..15 -> n
    int ty = tid >> 4;       // 0..15 -> m

    float acc[8][8];
    #pragma unroll
    for (int i = 0; i < 8; i++)
        #pragma unroll
        for (int jj = 0; jj < 8; jj++) acc[i][jj] = 0.0f;

    for (int k0 = 0; k0 < INDIM; k0 += 16) {
        #pragma unroll
        for (int i = 0; i < 2; i++) {
            int fidx = tid * 2 + i;          // 0..511
            int row = fidx >> 2;             // 0..127
            int kq  = fidx & 3;              // 0..3
            float4 v = *(const float4*)(A + (size_t)(bm + row) * INDIM + k0 + kq * 4);
            As[kq * 4 + 0][row] = v.x;
            As[kq * 4 + 1][row] = v.y;
            As[kq * 4 + 2][row] = v.z;
            As[kq * 4 + 3][row] = v.w;
            float4 u = *(const float4*)(B + (size_t)(bn + row) * INDIM + k0 + kq * 4);
            Bs[kq * 4 + 0][row] = u.x;
            Bs[kq * 4 + 1][row] = u.y;
            Bs[kq * 4 + 2][row] = u.z;
            Bs[kq * 4 + 3][row] = u.w;
        }
        __syncthreads();

        #pragma unroll
        for (int k = 0; k < 16; k++) {
            float a[8], b[8];
            *(float4*)(a)     = *(const float4*)&As[k][ty * 8];
            *(float4*)(a + 4) = *(const float4*)&As[k][ty * 8 + 4];
            *(float4*)(b)     = *(const float4*)&Bs[k][tx * 8];
            *(float4*)(b + 4) = *(const float4*)&Bs[k][tx * 8 + 4];
            #pragma unroll
            for (int mi = 0; mi < 8; mi++)
                #pragma unroll
                for (int ni = 0; ni < 8; ni++)
                    acc[mi][ni] += a[mi] * b[ni];
        }
        __syncthreads();
    }

    float bias[8];
    #pragma unroll
    for (int ni = 0; ni < 8; ni++) {
        int n = bn + tx * 8 + ni;
        bias[ni] = b_ih[n] + b_hh[n];
    }
    #pragma unroll
    for (int mi = 0; mi < 8; mi++) {
        int m = bm + ty * 8 + mi;
        float* cp = &g_xp[s][m][bn + tx * 8];
        float4 v0, v1;
        v0.x = acc[mi][0] + bias[0]; v0.y = acc[mi][1] + bias[1];
        v0.z = acc[mi][2] + bias[2]; v0.w = acc[mi][3] + bias[3];
        v1.x = acc[mi][4] + bias[4]; v1.y = acc[mi][5] + bias[5];
        v1.z = acc[mi][6] + bias[6]; v1.w = acc[mi][7] + bias[7];
        *(float4*)(cp)     = v0;
        *(float4*)(cp + 4) = v1;
    }
}

// ---------------- kernel 2: persistent LSTM scan, data-flow synced ----------------
// 128 CTAs: [0,64) = side L, [64,128) = side R. 8 warps/CTA, 1 warp = 1 hidden unit.
// Step t: every thread i polls tagged pairs 2i,2i+1 of buf[t&1] for tag==t,
// stages into SMEM (double-buffered), computes, lane0 stores {h, t+1} to buf[(t+1)&1].
// No fences, counters, or atomics anywhere in the scan.
__global__ void __launch_bounds__(256) scan_kernel(const float* __restrict__ W_hh,
                                                   float* __restrict__ out) {
    const int side = blockIdx.x >> 6;          // /64
    const int cta  = blockIdx.x & 63;
    const int warp = threadIdx.x >> 5;
    const int lane = threadIdx.x & 31;
    const int tid  = threadIdx.x;
    const int j = cta * 8 + warp;              // hidden unit 0..511

    // Load recurrent weights into registers (one time)
    float w[4][16];
    #pragma unroll
    for (int g = 0; g < 4; g++) {
        const float* row = W_hh + (size_t)(g * H + j) * H + lane * 16;
        #pragma unroll
        for (int q = 0; q < 4; q++) {
            float4 v = *(const float4*)(row + q * 4);
            w[g][q * 4 + 0] = v.x; w[g][q * 4 + 1] = v.y;
            w[g][q * 4 + 2] = v.z; w[g][q * 4 + 3] = v.w;
        }
    }

    __shared__ float sh[2][H];                 // double-buffered staged h
    const float* xps = &g_xp[side][0][0];
    float c = 0.0f;

    for (int t = 0; t < SEQ; t++) {
        const int rb = t & 1;

        // xp for this unit at step t (read-only, L1-cacheable, uniform in warp).
        // Issued before the poll so its latency hides under the wait.
        const float* xn = xps + (size_t)t * R4H;
        float xg0 = __ldg(xn + 0 * H + j);
        float xg1 = __ldg(xn + 1 * H + j);
        float xg2 = __ldg(xn + 2 * H + j);
        float xg3 = __ldg(xn + 3 * H + j);

        // Poll own two tagged pairs; stage values into SMEM.
        float v0 = poll_pair(&g_ht[side][rb][2 * tid],     (unsigned)t);
        float v1 = poll_pair(&g_ht[side][rb][2 * tid + 1], (unsigned)t);
        sh[rb][2 * tid]     = v0;
        sh[rb][2 * tid + 1] = v1;
        __syncthreads();

        // Each lane: 16 consecutive h values from SMEM
        float hr[16];
        const float4* sh4 = (const float4*)sh[rb];
        #pragma unroll
        for (int q = 0; q < 4; q++) {
            float4 v = sh4[lane * 4 + q];
            hr[q * 4 + 0] = v.x; hr[q * 4 + 1] = v.y;
            hr[q * 4 + 2] = v.z; hr[q * 4 + 3] = v.w;
        }

        float acc0 = 0.0f, acc1 = 0.0f, acc2 = 0.0f, acc3 = 0.0f;
        #pragma unroll
        for (int i = 0; i < 16; i++) {
            acc0 += w[0][i] * hr[i];
            acc1 += w[1][i] * hr[i];
            acc2 += w[2][i] * hr[i];
            acc3 += w[3][i] * hr[i];
        }
        // warp-wide sum (butterfly leaves total in every lane)
        #pragma unroll
        for (int off = 16; off > 0; off >>= 1) {
            acc0 += __shfl_xor_sync(0xFFFFFFFFu, acc0, off);
            acc1 += __shfl_xor_sync(0xFFFFFFFFu, acc1, off);
            acc2 += __shfl_xor_sync(0xFFFFFFFFu, acc2, off);
            acc3 += __shfl_xor_sync(0xFFFFFFFFu, acc3, off);
        }

        float gi = fast_sigmoid(acc0 + xg0);
        float gf = fast_sigmoid(acc1 + xg1);
        float gg = fast_tanh(acc2 + xg2);
        float go = fast_sigmoid(acc3 + xg3);
        c = gf * c + gi * gg;
        float hval = go * fast_tanh(c);
        if (lane == 0)
            store_pair(&g_ht[side][rb ^ 1][j], hval, (unsigned)(t + 1));
        // No trailing barrier: SMEM is double-buffered; overwrite of buf[rb] in
        // GMEM can't happen until all CTAs published tag t+2 (one-buffer slack).
    }

    // Final: block 0 polls both sides' final tags (SEQ) and reduces. Others exit.
    if (blockIdx.x == 0) {
        __shared__ float sred[8];
        // final h (after step SEQ-1) lives in buf[SEQ & 1] = buf[0] with tag SEQ.
        float l0 = poll_pair(&g_ht[0][0][2 * tid],     (unsigned)SEQ);
        float l1 = poll_pair(&g_ht[0][0][2 * tid + 1], (unsigned)SEQ);
        float r0 = poll_pair(&g_ht[1][0][2 * tid],     (unsigned)SEQ);
        float r1 = poll_pair(&g_ht[1][0][2 * tid + 1], (unsigned)SEQ);
        float sv = fabsf(l0 - r0) + fabsf(l1 - r1);
        #pragma unroll
        for (int off = 16; off > 0; off >>= 1)
            sv += __shfl_xor_sync(0xFFFFFFFFu, sv, off);
        if (lane == 0) sred[warp] = sv;
        __syncthreads();
        if (tid == 0) {
            float s = 0.0f;
            #pragma unroll
            for (int wdx = 0; wdx < 8; wdx++) s += sred[wdx];
            out[0] = expf(-s);   // accurate expf for the single final value
        }
    }
}

// ---------------- launch ----------------
extern "C" void kernel_launch(void* const* d_in, const int* in_sizes, int n_in,
                              void* d_out, int out_size) {
    const int* lidx = (const int*)d_in[0];
    const int* ridx = (const int*)d_in[1];
    const float* emb  = (const float*)d_in[2];
    const float* W_ih = (const float*)d_in[3];
    const float* W_hh = (const float*)d_in[4];
    const float* b_ih = (const float*)d_in[5];
    const float* b_hh = (const float*)d_in[6];
    float* out = (float*)d_out;

    init_gather<<<4096, 256>>>(lidx, ridx, emb);
    gemm_xp<<<dim3(16, 16, 2), 256>>>(W_ih, b_ih, b_hh);
    scan_kernel<<<TOTAL_CTAS, 256>>>(W_hh, out);
}

// round 7
// speedup vs baseline: 3.8855x; 1.3546x over previous
#include <cuda_runtime.h>
#include <cuda_bf16.h>
#include <math.h>

// Problem constants
#define SEQ   2048
#define INDIM 256
#define H     512
#define R4H   2048   // 4*H
#define CTAS_PER_SIDE 64
#define TOTAL_CTAS    128

// ---------------- device scratch (static: no allocation allowed) ----------------
__device__ float g_x[2][SEQ][INDIM];   // gathered embeddings, 4 MB
__device__ float g_xp[2][SEQ][R4H];    // input projections + bias, 32 MB
// Tagged hidden state: [side][buf][unit] = {lo: f32 h value, hi: u32 step tag}
__device__ __align__(16) unsigned long long g_ht[2][2][H];

// ---------------- tagged pair helpers ----------------
__device__ __forceinline__ void store_pair(unsigned long long* p, float v, unsigned tag) {
    unsigned long long u = ((unsigned long long)tag << 32) | (unsigned long long)__float_as_uint(v);
    asm volatile("st.global.cg.b64 [%0], %1;" :: "l"(p), "l"(u) : "memory");
}
// Poll two adjacent pairs with ONE 16B load; returns both f32 values.
__device__ __forceinline__ float2 poll_pair2(const unsigned long long* p, unsigned tag) {
    unsigned long long u0, u1;
    do {
        asm volatile("ld.global.cg.v2.u64 {%0,%1}, [%2];"
                     : "=l"(u0), "=l"(u1) : "l"(p) : "memory");
    } while (((unsigned)(u0 >> 32) != tag) || ((unsigned)(u1 >> 32) != tag));
    return make_float2(__uint_as_float((unsigned)u0), __uint_as_float((unsigned)u1));
}

// fast activations (ex2-based, ~1e-6 rel err)
__device__ __forceinline__ float fast_sigmoid(float x) {
    return 1.0f / (1.0f + __expf(-x));
}
__device__ __forceinline__ float fast_tanh(float x) {
    return 1.0f - 2.0f / (__expf(2.0f * x) + 1.0f);
}

// ---------------- kernel 0: gather embeddings + reset tagged state ----------------
// Token indices are int32 (JAX materializes jnp.int64 as int32 with x64 disabled).
__global__ void __launch_bounds__(256) init_gather(const int* __restrict__ lidx,
                                                   const int* __restrict__ ridx,
                                                   const float* __restrict__ emb) {
    int bx = blockIdx.x;              // 0..4095
    int side = bx >> 11;              // 0..1
    int t = bx & (SEQ - 1);
    const int* idxp = side ? ridx : lidx;
    long long tok = (long long)idxp[t];
    g_x[side][t][threadIdx.x] = emb[tok * (long long)INDIM + threadIdx.x];

    if (bx == 0) {
        // buf0: value 0.0f, tag 0 (valid input for step 0). buf1: tag sentinel.
        int i = threadIdx.x;                          // 0..255
        for (int s = 0; s < 2; s++) {
            g_ht[s][0][2 * i]     = 0ull;
            g_ht[s][0][2 * i + 1] = 0ull;
            g_ht[s][1][2 * i]     = 0xFFFFFFFF00000000ull;
            g_ht[s][1][2 * i + 1] = 0xFFFFFFFF00000000ull;
        }
    }
}

// ---------------- kernel 1: xp = x @ W_ih^T + (b_ih + b_hh) ----------------
__global__ void __launch_bounds__(256) gemm_xp(const float* __restrict__ W_ih,
                                               const float* __restrict__ b_ih,
                                               const float* __restrict__ b_hh) {
    int s  = blockIdx.z;
    int bm = blockIdx.y * 128;   // t offset
    int bn = blockIdx.x * 128;   // r offset
    const float* A = &g_x[s][0][0];   // [2048][256]
    const float* B = W_ih;            // [2048][256]

    __shared__ float As[16][128];
    __shared__ float Bs[16][128];

    int tid = threadIdx.x;
    int tx = tid & 15;
    int ty = tid >> 4;

    float acc[8][8];
    #pragma unroll
    for (int i = 0; i < 8; i++)
        #pragma unroll
        for (int jj = 0; jj < 8; jj++) acc[i][jj] = 0.0f;

    for (int k0 = 0; k0 < INDIM; k0 += 16) {
        #pragma unroll
        for (int i = 0; i < 2; i++) {
            int fidx = tid * 2 + i;
            int row = fidx >> 2;
            int kq  = fidx & 3;
            float4 v = *(const float4*)(A + (size_t)(bm + row) * INDIM + k0 + kq * 4);
            As[kq * 4 + 0][row] = v.x;
            As[kq * 4 + 1][row] = v.y;
            As[kq * 4 + 2][row] = v.z;
            As[kq * 4 + 3][row] = v.w;
            float4 u = *(const float4*)(B + (size_t)(bn + row) * INDIM + k0 + kq * 4);
            Bs[kq * 4 + 0][row] = u.x;
            Bs[kq * 4 + 1][row] = u.y;
            Bs[kq * 4 + 2][row] = u.z;
            Bs[kq * 4 + 3][row] = u.w;
        }
        __syncthreads();

        #pragma unroll
        for (int k = 0; k < 16; k++) {
            float a[8], b[8];
            *(float4*)(a)     = *(const float4*)&As[k][ty * 8];
            *(float4*)(a + 4) = *(const float4*)&As[k][ty * 8 + 4];
            *(float4*)(b)     = *(const float4*)&Bs[k][tx * 8];
            *(float4*)(b + 4) = *(const float4*)&Bs[k][tx * 8 + 4];
            #pragma unroll
            for (int mi = 0; mi < 8; mi++)
                #pragma unroll
                for (int ni = 0; ni < 8; ni++)
                    acc[mi][ni] += a[mi] * b[ni];
        }
        __syncthreads();
    }

    float bias[8];
    #pragma unroll
    for (int ni = 0; ni < 8; ni++) {
        int n = bn + tx * 8 + ni;
        bias[ni] = b_ih[n] + b_hh[n];
    }
    #pragma unroll
    for (int mi = 0; mi < 8; mi++) {
        int m = bm + ty * 8 + mi;
        float* cp = &g_xp[s][m][bn + tx * 8];
        float4 v0, v1;
        v0.x = acc[mi][0] + bias[0]; v0.y = acc[mi][1] + bias[1];
        v0.z = acc[mi][2] + bias[2]; v0.w = acc[mi][3] + bias[3];
        v1.x = acc[mi][4] + bias[4]; v1.y = acc[mi][5] + bias[5];
        v1.z = acc[mi][6] + bias[6]; v1.w = acc[mi][7] + bias[7];
        *(float4*)(cp)     = v0;
        *(float4*)(cp + 4) = v1;
    }
}

// ---------------- kernel 2: persistent LSTM scan, data-flow synced ----------------
// 128 CTAs: [0,64) = side L, [64,128) = side R. 8 warps/CTA, 1 warp = 1 hidden unit.
// Recurrent dot products in bf16 (HFMA2); h published as tagged f32 pairs; no fences.
// Warp reduction: 7-shfl merge (4 gate sums -> one gate per 8-lane group),
// activations computed distributed, lane 0 gathers via 3 shfl.idx.
__global__ void __launch_bounds__(256) scan_kernel(const float* __restrict__ W_hh,
                                                   float* __restrict__ out) {
    const int side = blockIdx.x >> 6;
    const int cta  = blockIdx.x & 63;
    const int warp = threadIdx.x >> 5;
    const int lane = threadIdx.x & 31;
    const int tid  = threadIdx.x;
    const int j = cta * 8 + warp;              // hidden unit 0..511
    const unsigned FULL = 0xFFFFFFFFu;

    // gate owned by this lane after the merged reduction:
    // g = 2*b3 + b4  (b3 = lane bit 3, b4 = lane bit 4)
    const int b3 = (lane >> 3) & 1;
    const int b4 = (lane >> 4) & 1;
    const int mygate = 2 * b3 + b4;            // 0:i 1:f 2:g 3:o

    // Recurrent weights, converted once to bf16x2: w2[g][k] packs W[2k],W[2k+1]
    __nv_bfloat162 w2[4][8];
    #pragma unroll
    for (int g = 0; g < 4; g++) {
        const float2* row = (const float2*)(W_hh + (size_t)(g * H + j) * H + lane * 16);
        #pragma unroll
        for (int k = 0; k < 8; k++) {
            float2 p = row[k];
            w2[g][k] = __floats2bfloat162_rn(p.x, p.y);
        }
    }

    __shared__ __nv_bfloat162 sh2[2][H / 2];   // double-buffered staged h (bf16x2)
    const float* xps = &g_xp[side][0][0];
    float c = 0.0f;                            // live in lane 0 only

    for (int t = 0; t < SEQ; t++) {
        const int rb = t & 1;

        // xp for this lane's gate at step t (read-only; hides under the poll)
        const float* xn = xps + (size_t)t * R4H;
        float xg = __ldg(xn + mygate * H + j);

        // One 16B poll for both of this thread's pairs; stage as one bf16x2.
        float2 v = poll_pair2(&g_ht[side][rb][2 * tid], (unsigned)t);
        sh2[rb][tid] = __floats2bfloat162_rn(v.x, v.y);
        __syncthreads();

        // Lane reads its 16 h values = 8 bf16x2 (32 bytes) from SMEM
        __nv_bfloat162 h2[8];
        {
            const uint4* sp = (const uint4*)&sh2[rb][lane * 8];
            uint4 a = sp[0], b = sp[1];
            ((uint4*)h2)[0] = a;
            ((uint4*)h2)[1] = b;
        }

        __nv_bfloat162 a0 = __floats2bfloat162_rn(0.f, 0.f);
        __nv_bfloat162 a1 = a0, a2 = a0, a3 = a0;
        #pragma unroll
        for (int k = 0; k < 8; k++) {
            a0 = __hfma2(w2[0][k], h2[k], a0);
            a1 = __hfma2(w2[1][k], h2[k], a1);
            a2 = __hfma2(w2[2][k], h2[k], a2);
            a3 = __hfma2(w2[3][k], h2[k], a3);
        }
        float s0 = __low2float(a0) + __high2float(a0);
        float s1 = __low2float(a1) + __high2float(a1);
        float s2 = __low2float(a2) + __high2float(a2);
        float s3 = __low2float(a3) + __high2float(a3);

        // ---- merged reduction: 7 shfls, 5 rounds ----
        // Round 1 (xor 16): r01 <- gate0 partial in b4=0 lanes, gate1 in b4=1.
        float p01 = b4 ? s1 : s0;
        float q01 = b4 ? s0 : s1;
        float r01 = p01 + __shfl_xor_sync(FULL, q01, 16);
        float p23 = b4 ? s3 : s2;
        float q23 = b4 ? s2 : s3;
        float r23 = p23 + __shfl_xor_sync(FULL, q23, 16);
        // Round 2 (xor 8): merge the two chains; 8-lane group (b3,b4) owns gate 2*b3+b4.
        float p = b3 ? r23 : r01;
        float q = b3 ? r01 : r23;
        float r = p + __shfl_xor_sync(FULL, q, 8);
        // Rounds 3-5: reduce within the 8-lane group (bits 0-2 only).
        r += __shfl_xor_sync(FULL, r, 4);
        r += __shfl_xor_sync(FULL, r, 2);
        r += __shfl_xor_sync(FULL, r, 1);

        // ---- distributed activation: gate 2 -> tanh, else sigmoid ----
        float x = r + xg;
        bool is_tanh = (mygate == 2);
        float e = __expf(is_tanh ? (2.0f * x) : (-x));
        float num = is_tanh ? (e - 1.0f) : 1.0f;
        float act = num / (e + 1.0f);   // sigmoid(x) or tanh(x)

        // lane 0 gathers gates: i from itself, f from lane 16, g from lane 8, o from lane 24
        float gf = __shfl_sync(FULL, act, 16);
        float gg = __shfl_sync(FULL, act, 8);
        float go = __shfl_sync(FULL, act, 24);
        if (lane == 0) {
            c = gf * c + act * gg;           // act = gi in lane 0
            float hval = go * fast_tanh(c);
            store_pair(&g_ht[side][rb ^ 1][j], hval, (unsigned)(t + 1));
        }
        // One bar per step is sufficient (R4 proof: publish of tag t+1 by every
        // CTA gates all overwrites of tag t-1 data; SMEM double-buffered).
    }

    // Final: block 0 polls both sides' final tags (SEQ) and reduces.
    if (blockIdx.x == 0) {
        __shared__ float sred[8];
        float2 l = poll_pair2(&g_ht[0][0][2 * tid], (unsigned)SEQ);
        float2 r2 = poll_pair2(&g_ht[1][0][2 * tid], (unsigned)SEQ);
        float sv = fabsf(l.x - r2.x) + fabsf(l.y - r2.y);
        #pragma unroll
        for (int off = 16; off > 0; off >>= 1)
            sv += __shfl_xor_sync(FULL, sv, off);
        if (lane == 0) sred[warp] = sv;
        __syncthreads();
        if (tid == 0) {
            float s = 0.0f;
            #pragma unroll
            for (int wdx = 0; wdx < 8; wdx++) s += sred[wdx];
            out[0] = expf(-s);   // accurate expf for the single final value
        }
    }
}

// ---------------- launch ----------------
extern "C" void kernel_launch(void* const* d_in, const int* in_sizes, int n_in,
                              void* d_out, int out_size) {
    const int* lidx = (const int*)d_in[0];
    const int* ridx = (const int*)d_in[1];
    const float* emb  = (const float*)d_in[2];
    const float* W_ih = (const float*)d_in[3];
    const float* W_hh = (const float*)d_in[4];
    const float* b_ih = (const float*)d_in[5];
    const float* b_hh = (const float*)d_in[6];
    float* out = (float*)d_out;

    init_gather<<<4096, 256>>>(lidx, ridx, emb);
    gemm_xp<<<dim3(16, 16, 2), 256>>>(W_ih, b_ih, b_hh);
    scan_kernel<<<TOTAL_CTAS, 256>>>(W_hh, out);
}

// round 10
// speedup vs baseline: 4.5831x; 1.1795x over previous
#include <cuda_runtime.h>
#include <cuda_bf16.h>
#include <math.h>

// Problem constants
#define SEQ   2048
#define INDIM 256
#define H     512
#define CTAS_PER_SIDE 64
#define TOTAL_CTAS    128
#define RING  64
#define NTHREADS 384        // warps 0-3 producers, warps 4-11 consumers

// ---------------- device scratch (static: no allocation allowed) ----------------
__device__ __align__(16) float g_x[2][SEQ][INDIM];    // gathered embeddings, 4 MB
// Packed hidden state: [side][buf][unit] = {tag16 << 16 | bf16(h)}
__device__ __align__(16) unsigned g_hp[2][2][H];

// ---------------- packed publish/poll helpers ----------------
__device__ __forceinline__ void store_h(unsigned* p, float v, unsigned tag) {
    unsigned hb = (unsigned)__bfloat16_as_ushort(__float2bfloat16(v));
    unsigned u = (tag << 16) | hb;
    asm volatile("st.global.cg.u32 [%0], %1;" :: "l"(p), "r"(u) : "memory");
}
// Poll two adjacent units with one 8B load; returns packed bf16x2 (lo=unit0, hi=unit1).
__device__ __forceinline__ unsigned poll_h2(const unsigned* p, unsigned tag) {
    unsigned a, b;
    do {
        asm volatile("ld.global.cg.v2.u32 {%0,%1}, [%2];"
                     : "=r"(a), "=r"(b) : "l"(p) : "memory");
    } while ((a >> 16) != tag || (b >> 16) != tag);
    return (a & 0xFFFFu) | (b << 16);
}

__device__ __forceinline__ unsigned b2u(__nv_bfloat162 v) { return *(unsigned*)&v; }
__device__ __forceinline__ __nv_bfloat162 u2b(unsigned u) { return *(__nv_bfloat162*)&u; }

// fast activations (ex2-based, ~1e-6 rel err)
__device__ __forceinline__ float fast_tanh(float x) {
    return 1.0f - 2.0f / (__expf(2.0f * x) + 1.0f);
}

// ---------------- kernel 0: gather embeddings + reset packed state ----------------
// Token indices are int32 (JAX materializes jnp.int64 as int32 with x64 disabled).
__global__ void __launch_bounds__(256) init_gather(const int* __restrict__ lidx,
                                                   const int* __restrict__ ridx,
                                                   const float* __restrict__ emb) {
    int bx = blockIdx.x;              // 0..4095
    int side = bx >> 11;
    int t = bx & (SEQ - 1);
    const int* idxp = side ? ridx : lidx;
    long long tok = (long long)idxp[t];
    g_x[side][t][threadIdx.x] = emb[tok * (long long)INDIM + threadIdx.x];

    if (bx == 0) {
        int i = threadIdx.x;          // 0..255
        for (int s = 0; s < 2; s++) {
            // buf0: tag 0, h = bf16(0) -> word 0. buf1: sentinel tag 0xFFFF.
            g_hp[s][0][2 * i]     = 0u;
            g_hp[s][0][2 * i + 1] = 0u;
            g_hp[s][1][2 * i]     = 0xFFFF0000u;
            g_hp[s][1][2 * i + 1] = 0xFFFF0000u;
        }
    }
}

// ---------------- kernel 1: fused producer/consumer persistent scan ----------------
// 128 CTAs x 384 threads. Warps 0-3 (low priority) produce this CTA's 32 xp
// columns (xp = x @ W_ih^T + b for units j..j+7, gates 0..3) into an SMEM ring,
// ~64 steps ahead. Warps 4-11 (high priority) run the LSTM step exactly as R7:
// poll packed h tags, stage to SMEM, HFMA2 dots, 7-shfl merged reduce,
// distributed activations, lane0 publishes packed {tag,bf16 h}.
__global__ void __launch_bounds__(NTHREADS, 1) scan_kernel(const float* __restrict__ W_ih,
                                                           const float* __restrict__ W_hh,
                                                           const float* __restrict__ b_ih,
                                                           const float* __restrict__ b_hh,
                                                           float* __restrict__ out) {
    const int side = blockIdx.x >> 6;
    const int cta  = blockIdx.x & 63;
    const int wid  = threadIdx.x >> 5;
    const int lane = threadIdx.x & 31;
    const unsigned FULL = 0xFFFFFFFFu;

    // ---- shared state (16B-aligned: several arrays are read with uint4/float4) ----
    __shared__ __align__(16) unsigned wpcT[128][32];  // producer W_ih cols, bf16x2
    __shared__ __align__(16) unsigned xstage[4][128]; // per producer warp: x[t] bf16x2
    __shared__ __align__(16) unsigned sh2[2][H / 2];  // double-buffered staged h words
    __shared__ __align__(16) float    ring[RING][32]; // xp ring: [t mod 64][col]
    __shared__ float    bias_s[32];
    __shared__ float    sred[8];
    __shared__ volatile int ring_tag[RING];
    __shared__ volatile int scons;                    // last step fully consumed

    // ---- cooperative setup (all 384 threads) ----
    // wpcT[p][c] = bf16x2 of W_ih[row(c)][2p], [2p+1]; row(c) = (c/8)*512 + cta*8 + (c%8)
    for (int idx = threadIdx.x; idx < 128 * 32; idx += NTHREADS) {
        int c = idx & 31;
        int p = idx >> 5;
        int row = (c >> 3) * H + cta * 8 + (c & 7);
        float2 wv = *(const float2*)(W_ih + (size_t)row * INDIM + 2 * p);
        wpcT[p][c] = b2u(__floats2bfloat162_rn(wv.x, wv.y));
    }
    if (threadIdx.x < 32) {
        int c = threadIdx.x;
        int row = (c >> 3) * H + cta * 8 + (c & 7);
        bias_s[c] = b_ih[row] + b_hh[row];
    }
    for (int s = threadIdx.x; s < RING; s += NTHREADS) ring_tag[s] = -1;
    if (threadIdx.x == 0) scons = -1;
    __syncthreads();   // the ONLY full-CTA barrier

    if (wid < 4) {
        // ================= PRODUCER =================
        const int p = wid;
        for (int t = p; t < SEQ; t += 4) {
            while (scons < t - RING) { }   // ring backpressure (SMEM spin)

            // load x[t][lane*8 .. +7], convert to 4 bf16x2, stage for broadcast
            const float4* xp4 = (const float4*)&g_x[side][t][lane * 8];
            float4 v1 = __ldg(xp4);
            float4 v2 = __ldg(xp4 + 1);
            xstage[p][lane * 4 + 0] = b2u(__floats2bfloat162_rn(v1.x, v1.y));
            xstage[p][lane * 4 + 1] = b2u(__floats2bfloat162_rn(v1.z, v1.w));
            xstage[p][lane * 4 + 2] = b2u(__floats2bfloat162_rn(v2.x, v2.y));
            xstage[p][lane * 4 + 3] = b2u(__floats2bfloat162_rn(v2.z, v2.w));
            __syncwarp();

            // lane = col; dot over 128 k-pairs, 4 bf16x2 partial accumulators
            __nv_bfloat162 a0 = __floats2bfloat162_rn(0.f, 0.f);
            __nv_bfloat162 a1 = a0, a2 = a0, a3 = a0;
            #pragma unroll
            for (int s = 0; s < 32; s++) {
                uint4 xv = *(const uint4*)&xstage[p][s * 4];   // broadcast (16B)
                a0 = __hfma2(u2b(wpcT[s * 4 + 0][lane]), u2b(xv.x), a0);
                a1 = __hfma2(u2b(wpcT[s * 4 + 1][lane]), u2b(xv.y), a1);
                a2 = __hfma2(u2b(wpcT[s * 4 + 2][lane]), u2b(xv.z), a2);
                a3 = __hfma2(u2b(wpcT[s * 4 + 3][lane]), u2b(xv.w), a3);
            }
            float sum = (__low2float(a0) + __high2float(a0))
                      + (__low2float(a1) + __high2float(a1))
                      + (__low2float(a2) + __high2float(a2))
                      + (__low2float(a3) + __high2float(a3))
                      + bias_s[lane];
            ring[t & (RING - 1)][lane] = sum;
            __syncwarp();
            if (lane == 0) {
                asm volatile("membar.cta;" ::: "memory");
                ring_tag[t & (RING - 1)] = t;
            }
            __syncwarp();   // reads of xstage done before next iteration restages
        }
        return;
    }

    // ================= CONSUMER =================
    const int cw    = wid - 4;                  // 0..7
    const int jj    = cw;                       // unit within CTA
    const int j     = cta * 8 + jj;             // hidden unit 0..511
    const int tid_c = threadIdx.x - 128;        // 0..255

    const int b3 = (lane >> 3) & 1;
    const int b4 = (lane >> 4) & 1;
    const int mygate = 2 * b3 + b4;             // 0:i 1:f 2:g 3:o

    // recurrent weights -> bf16x2 registers (one time)
    unsigned w2[4][8];
    #pragma unroll
    for (int g = 0; g < 4; g++) {
        const float2* row = (const float2*)(W_hh + (size_t)(g * H + j) * H + lane * 16);
        #pragma unroll
        for (int k = 0; k < 8; k++) {
            float2 pv = row[k];
            w2[g][k] = b2u(__floats2bfloat162_rn(pv.x, pv.y));
        }
    }

    float c = 0.0f;                             // live in lane 0 only

    for (int t = 0; t < SEQ; t++) {
        const int rb = t & 1;
        const int slot = t & (RING - 1);

        // xp from SMEM ring (producers run ~64 steps ahead; normally instant)
        while (ring_tag[slot] != t) { }
        float xg = ring[slot][mygate * 8 + jj];

        // poll own two packed units; stage bf16x2 word directly
        unsigned hp = poll_h2(&g_hp[side][rb][2 * tid_c], (unsigned)t);
        sh2[rb][tid_c] = hp;
        asm volatile("bar.sync 1, 256;" ::: "memory");
        if (tid_c == 0) scons = t;              // all consumers past ring read

        // lane reads its 16 h values = 8 bf16x2 words (32B) from SMEM
        uint4 ha = ((const uint4*)&sh2[rb][lane * 8])[0];
        uint4 hb = ((const uint4*)&sh2[rb][lane * 8])[1];

        __nv_bfloat162 a0 = __floats2bfloat162_rn(0.f, 0.f);
        __nv_bfloat162 a1 = a0, a2 = a0, a3 = a0;
        unsigned hw[8] = {ha.x, ha.y, ha.z, ha.w, hb.x, hb.y, hb.z, hb.w};
        #pragma unroll
        for (int k = 0; k < 8; k++) {
            __nv_bfloat162 hv = u2b(hw[k]);
            a0 = __hfma2(u2b(w2[0][k]), hv, a0);
            a1 = __hfma2(u2b(w2[1][k]), hv, a1);
            a2 = __hfma2(u2b(w2[2][k]), hv, a2);
            a3 = __hfma2(u2b(w2[3][k]), hv, a3);
        }
        float s0 = __low2float(a0) + __high2float(a0);
        float s1 = __low2float(a1) + __high2float(a1);
        float s2 = __low2float(a2) + __high2float(a2);
        float s3 = __low2float(a3) + __high2float(a3);

        // merged reduction: 7 shfls, 5 rounds (R7)
        float p01 = b4 ? s1 : s0;
        float q01 = b4 ? s0 : s1;
        float r01 = p01 + __shfl_xor_sync(FULL, q01, 16);
        float p23 = b4 ? s3 : s2;
        float q23 = b4 ? s2 : s3;
        float r23 = p23 + __shfl_xor_sync(FULL, q23, 16);
        float pq = b3 ? r23 : r01;
        float qq = b3 ? r01 : r23;
        float r = pq + __shfl_xor_sync(FULL, qq, 8);
        r += __shfl_xor_sync(FULL, r, 4);
        r += __shfl_xor_sync(FULL, r, 2);
        r += __shfl_xor_sync(FULL, r, 1);

        // distributed activation: gate 2 -> tanh, else sigmoid
        float x = r + xg;
        bool is_tanh = (mygate == 2);
        float e = __expf(is_tanh ? (2.0f * x) : (-x));
        float num = is_tanh ? (e - 1.0f) : 1.0f;
        float act = num / (e + 1.0f);

        float gf = __shfl_sync(FULL, act, 16);
        float gg = __shfl_sync(FULL, act, 8);
        float go = __shfl_sync(FULL, act, 24);
        if (lane == 0) {
            c = gf * c + act * gg;              // act = gi in lane 0
            float hval = go * fast_tanh(c);
            store_h(&g_hp[side][rb ^ 1][j], hval, (unsigned)(t + 1));
        }
    }

    // Final: block 0's consumers poll both sides' final tags (SEQ=2048) and reduce.
    if (blockIdx.x == 0) {
        unsigned lp = poll_h2(&g_hp[0][0][2 * tid_c], (unsigned)SEQ);
        unsigned rp = poll_h2(&g_hp[1][0][2 * tid_c], (unsigned)SEQ);
        __nv_bfloat162 lv = u2b(lp), rv = u2b(rp);
        float sv = fabsf(__low2float(lv) - __low2float(rv))
                 + fabsf(__high2float(lv) - __high2float(rv));
        #pragma unroll
        for (int off = 16; off > 0; off >>= 1)
            sv += __shfl_xor_sync(FULL, sv, off);
        if (lane == 0) sred[cw] = sv;
        asm volatile("bar.sync 1, 256;" ::: "memory");
        if (tid_c == 0) {
            float s = 0.0f;
            #pragma unroll
            for (int wdx = 0; wdx < 8; wdx++) s += sred[wdx];
            out[0] = expf(-s);
        }
    }
}

// ---------------- launch ----------------
extern "C" void kernel_launch(void* const* d_in, const int* in_sizes, int n_in,
                              void* d_out, int out_size) {
    const int* lidx = (const int*)d_in[0];
    const int* ridx = (const int*)d_in[1];
    const float* emb  = (const float*)d_in[2];
    const float* W_ih = (const float*)d_in[3];
    const float* W_hh = (const float*)d_in[4];
    const float* b_ih = (const float*)d_in[5];
    const float* b_hh = (const float*)d_in[6];
    float* out = (float*)d_out;

    init_gather<<<4096, 256>>>(lidx, ridx, emb);
    scan_kernel<<<TOTAL_CTAS, NTHREADS>>>(W_ih, W_hh, b_ih, b_hh, out);
}